// round 2
// baseline (speedup 1.0000x reference)
#include <cuda_runtime.h>
#include <math.h>

#define NN 50000
#define NE 800000
#define NG 1024
#define NP 16384
#define NC 16
#define INCH 64
#define EMB 128
#define HID 256
#define BUCKET_SLOTS ((NP / 32 + NC) * 32)   // 16896
#define REG_BLOCKS (NP / 32 + NC)            // 528

// ---------------- scratch (static device memory; no runtime allocation) ----------------
__device__ float g_deg[NN];
__device__ float g_dinv[NN];
__device__ float g_hws[NN * EMB];
__device__ float g_tmp[NN * EMB];
__device__ float g_act[NN * EMB];
__device__ float g_gsum[NG * EMB];
__device__ float g_cnt[NG];
__device__ float g_ge[NG * EMB];
__device__ int   g_counts[NC];
__device__ int   g_cursor[NC];
__device__ int   g_pstart[NC + 1];
__device__ int   g_bucket[BUCKET_SLOTS];

// ---------------- helpers ----------------
__device__ __forceinline__ void red_add_v4(float* addr, float4 v) {
    asm volatile("red.global.add.v4.f32 [%0], {%1, %2, %3, %4};"
                 :: "l"(addr), "f"(v.x), "f"(v.y), "f"(v.z), "f"(v.w)
                 : "memory");
}

// ---------------- degree / norm ----------------
__global__ void k_init_deg() {
    int i = blockIdx.x * blockDim.x + threadIdx.x;
    if (i < NN) g_deg[i] = 1.0f;  // self-loop
}

__global__ void k_deg(const int* __restrict__ ei) {
    int e = blockIdx.x * blockDim.x + threadIdx.x;
    if (e < NE) atomicAdd(&g_deg[ei[NE + e]], 1.0f);  // col = target
}

__global__ void k_dinv() {
    int i = blockIdx.x * blockDim.x + threadIdx.x;
    if (i < NN) g_dinv[i] = rsqrtf(g_deg[i]);
}

// ---------------- GEMM:  hws = dinv ⊙ (X @ W);  tmp = hws (self-loop init) ----------------
// X: [NN, K], W: [K, 128]. Block = 256 threads (8 warps). Each warp handles one row
// at a time; lane computes 4 consecutive output columns.
template <int K, int BM>
__global__ void k_gemm(const float* __restrict__ X, const float* __restrict__ W) {
    extern __shared__ float sm[];
    float* sW = sm;            // K * 128
    float* sX = sm + K * 128;  // BM * K

    int tid = threadIdx.x;
    for (int i = tid; i < K * 128; i += 256) sW[i] = W[i];

    int row0 = blockIdx.x * BM;
    for (int i = tid; i < BM * K; i += 256) {
        int r = i / K, k = i - r * K;
        int gr = row0 + r;
        sX[i] = (gr < NN) ? X[gr * K + k] : 0.0f;
    }
    __syncthreads();

    int warp = tid >> 5, lane = tid & 31;
    for (int r = warp; r < BM; r += 8) {
        int gr = row0 + r;
        if (gr >= NN) break;
        float4 acc = make_float4(0.f, 0.f, 0.f, 0.f);
        const float* xr = &sX[r * K];
#pragma unroll 8
        for (int k = 0; k < K; k++) {
            float xk = xr[k];
            float4 wv = *(const float4*)&sW[k * 128 + lane * 4];
            acc.x = fmaf(xk, wv.x, acc.x);
            acc.y = fmaf(xk, wv.y, acc.y);
            acc.z = fmaf(xk, wv.z, acc.z);
            acc.w = fmaf(xk, wv.w, acc.w);
        }
        float d = g_dinv[gr];
        acc.x *= d; acc.y *= d; acc.z *= d; acc.w *= d;
        *(float4*)&g_hws[gr * EMB + lane * 4] = acc;
        *(float4*)&g_tmp[gr * EMB + lane * 4] = acc;   // self-loop contribution
    }
}

// ---------------- edge scatter: tmp[col] += hws[row] (one warp per edge) ----------------
__global__ void k_scatter(const int* __restrict__ ei) {
    int w = (blockIdx.x * blockDim.x + threadIdx.x) >> 5;
    int lane = threadIdx.x & 31;
    if (w >= NE) return;
    int r = ei[w];        // source
    int c = ei[NE + w];   // target
    float4 v = *(const float4*)&g_hws[r * EMB + lane * 4];
    red_add_v4(&g_tmp[c * EMB + lane * 4], v);
}

// ---------------- finalize: act = relu(dinv ⊙ tmp + b) ----------------
__global__ void k_finalize(const float* __restrict__ b) {
    int i = blockIdx.x * blockDim.x + threadIdx.x;
    if (i < NN * EMB) {
        int node = i >> 7, j = i & 127;
        g_act[i] = fmaxf(fmaf(g_dinv[node], g_tmp[i], b[j]), 0.0f);
    }
}

// ---------------- graph pooling ----------------
__global__ void k_zero_graph() {
    int i = blockIdx.x * blockDim.x + threadIdx.x;
    if (i < NG * EMB) g_gsum[i] = 0.0f;
    if (i < NG) g_cnt[i] = 0.0f;
}

__global__ void k_pool(const int* __restrict__ batch) {
    int w = (blockIdx.x * blockDim.x + threadIdx.x) >> 5;
    int lane = threadIdx.x & 31;
    if (w >= NN) return;
    int g = batch[w];
    float4 v = *(const float4*)&g_act[w * EMB + lane * 4];
    red_add_v4(&g_gsum[g * EMB + lane * 4], v);
    if (lane == 0) atomicAdd(&g_cnt[g], 1.0f);
}

__global__ void k_ge() {
    int i = blockIdx.x * blockDim.x + threadIdx.x;
    if (i < NG * EMB) g_ge[i] = g_gsum[i] / fmaxf(g_cnt[i >> 7], 1.0f);
}

// ---------------- pair bucketing by cell line ----------------
__global__ void k_zero_bucket() {
    int i = blockIdx.x * blockDim.x + threadIdx.x;
    if (i < BUCKET_SLOTS) g_bucket[i] = -1;
    if (i < NC) { g_counts[i] = 0; g_cursor[i] = 0; }
}

__global__ void k_count(const int* __restrict__ ecl) {
    int p = blockIdx.x * blockDim.x + threadIdx.x;
    if (p < NP) atomicAdd(&g_counts[ecl[p]], 1);
}

__global__ void k_prefix() {
    int acc = 0;
    for (int c = 0; c < NC; c++) {
        g_pstart[c] = acc;
        acc += ((g_counts[c] + 31) / 32) * 32;
    }
    g_pstart[NC] = acc;
}

__global__ void k_scatter_pairs(const int* __restrict__ ecl) {
    int p = blockIdx.x * blockDim.x + threadIdx.x;
    if (p < NP) {
        int c = ecl[p];
        int pos = g_pstart[c] + atomicAdd(&g_cursor[c], 1);
        g_bucket[pos] = p;
    }
}

// ---------------- per-cell-line regressor: 32 pairs per block ----------------
__global__ void __launch_bounds__(256) k_reg(
    const int* __restrict__ ddb, const int* __restrict__ ecl,
    const float* __restrict__ w1, const float* __restrict__ b1,
    const float* __restrict__ w2, const float* __restrict__ b2,
    float* __restrict__ out)
{
    __shared__ int   s_pid[32];
    __shared__ float s_pair[32][HID];   // 32 KB; reused as reduce scratch

    int tid = threadIdx.x;
    int base = blockIdx.x * 32;
    if (tid < 32) s_pid[tid] = g_bucket[base + tid];
    __syncthreads();

    int c = -1;
    for (int s = 0; s < 32 && c < 0; s++) {
        int p = s_pid[s];
        if (p >= 0) c = ecl[p];
    }
    if (c < 0) return;  // fully-padding block (uniform exit)

    // gather pair tile: [32 pairs][256] = concat(ge[q0], ge[q1])
    for (int i = tid; i < 32 * HID; i += 256) {
        int s = i >> 8, j = i & 255;
        int p = s_pid[s];
        float v = 0.0f;
        if (p >= 0) {
            int q = (j < 128) ? ddb[p] : ddb[NP + p];
            v = g_ge[q * EMB + (j & 127)];
        }
        s_pair[s][j] = v;
    }
    __syncthreads();

    const float* W = w1 + c * (HID * HID);   // [e][h], h contiguous
    float bt = b1[c * HID + tid];
    float acc[32];
#pragma unroll
    for (int s = 0; s < 32; s++) acc[s] = bt;

    for (int e = 0; e < HID; e += 4) {
        float wa = W[(e + 0) * HID + tid];
        float wb = W[(e + 1) * HID + tid];
        float wc = W[(e + 2) * HID + tid];
        float wd = W[(e + 3) * HID + tid];
#pragma unroll
        for (int s = 0; s < 32; s++) {
            float4 pv = *(const float4*)&s_pair[s][e];
            acc[s] = fmaf(pv.x, wa, fmaf(pv.y, wb, fmaf(pv.z, wc, fmaf(pv.w, wd, acc[s]))));
        }
    }

    float w2v = w2[c * HID + tid];
    __syncthreads();
#pragma unroll
    for (int s = 0; s < 32; s++) s_pair[s][tid] = fmaxf(acc[s], 0.0f) * w2v;
    __syncthreads();

    // 32 reductions of 256 values: 8 threads per pair, 32 values each, then shfl within 8
    int s = tid >> 3, g = tid & 7;
    const float* rowp = &s_pair[s][g * 32];
    float sum = 0.0f;
#pragma unroll
    for (int j = 0; j < 32; j++) sum += rowp[j];
    sum += __shfl_down_sync(0xffffffffu, sum, 4, 8);
    sum += __shfl_down_sync(0xffffffffu, sum, 2, 8);
    sum += __shfl_down_sync(0xffffffffu, sum, 1, 8);
    if (g == 0) {
        int p = s_pid[s];
        if (p >= 0) out[p] = sum + b2[c];
    }
}

// ---------------- host launch ----------------
extern "C" void kernel_launch(void* const* d_in, const int* in_sizes, int n_in,
                              void* d_out, int out_size)
{
    const float* x    = (const float*)d_in[0];
    const float* c1w  = (const float*)d_in[1];
    const float* c1b  = (const float*)d_in[2];
    const float* c2w  = (const float*)d_in[3];
    const float* c2b  = (const float*)d_in[4];
    const float* rw1  = (const float*)d_in[5];
    const float* rb1  = (const float*)d_in[6];
    const float* rw2  = (const float*)d_in[7];
    const float* rb2  = (const float*)d_in[8];
    const int*   ei   = (const int*)d_in[9];
    const int*   bat  = (const int*)d_in[10];
    const int*   ddb  = (const int*)d_in[11];
    const int*   ecl  = (const int*)d_in[12];
    float* out = (float*)d_out;

    // opt-in shared memory sizes (host attr calls; not stream ops, capture-safe)
    cudaFuncSetAttribute(k_gemm<64, 64>,  cudaFuncAttributeMaxDynamicSharedMemorySize, 49152);
    cudaFuncSetAttribute(k_gemm<128, 32>, cudaFuncAttributeMaxDynamicSharedMemorySize, 81920);

    float* act_ptr = nullptr;
    cudaGetSymbolAddress((void**)&act_ptr, g_act);

    const int T = 256;

    // degrees / normalization
    k_init_deg<<<(NN + T - 1) / T, T>>>();
    k_deg<<<(NE + T - 1) / T, T>>>(ei);
    k_dinv<<<(NN + T - 1) / T, T>>>();

    // layer 1: x[50000,64] @ W[64,128]
    k_gemm<64, 64><<<(NN + 63) / 64, T, 49152>>>(x, c1w);
    k_scatter<<<(NE * 32 + T - 1) / T, T>>>(ei);
    k_finalize<<<(NN * EMB + T - 1) / T, T>>>(c1b);

    // layer 2: act[50000,128] @ W[128,128]
    k_gemm<128, 32><<<(NN + 31) / 32, T, 81920>>>(act_ptr, c2w);
    k_scatter<<<(NE * 32 + T - 1) / T, T>>>(ei);
    k_finalize<<<(NN * EMB + T - 1) / T, T>>>(c2b);

    // scatter-mean pooling
    k_zero_graph<<<(NG * EMB + T - 1) / T, T>>>();
    k_pool<<<(NN * 32 + T - 1) / T, T>>>(bat);
    k_ge<<<(NG * EMB + T - 1) / T, T>>>();

    // bucket pairs by cell line (padded to 32-pair tiles)
    k_zero_bucket<<<(BUCKET_SLOTS + T - 1) / T, T>>>();
    k_count<<<(NP + T - 1) / T, T>>>(ecl);
    k_prefix<<<1, 1>>>();
    k_scatter_pairs<<<(NP + T - 1) / T, T>>>(ecl);

    // regressor
    k_reg<<<REG_BLOCKS, T>>>(ddb, ecl, rw1, rb1, rw2, rb2, out);
}

// round 3
// speedup vs baseline: 1.5382x; 1.5382x over previous
#include <cuda_runtime.h>
#include <math.h>

#define NN 50000
#define NE 800000
#define NG 1024
#define NP 16384
#define NC 16
#define INCH 64
#define EMB 128
#define HID 256
#define BUCKET_SLOTS ((NP / 32 + NC) * 32)   // 16896
#define REG_BLOCKS (NP / 32 + NC)            // 528

// ---------------- scratch (static device memory) ----------------
__device__ float g_deg[NN];
__device__ float g_dinv[NN];
__device__ float g_xs[NN * INCH];      // dinv ⊙ x (layer-1 scatter source)
__device__ float g_tmp64[NN * INCH];   // layer-1 aggregation target
__device__ float g_hws[NN * EMB];      // dinv ⊙ h1 (layer-2 scatter source)
__device__ float g_tmp[NN * EMB];      // layer-2 aggregation target
__device__ float g_gsum[NG * EMB];
__device__ float g_cnt[NG];
__device__ float g_ge[NG * EMB];
__device__ int   g_counts[NC];
__device__ int   g_cursor[NC];
__device__ int   g_pstart[NC + 1];
__device__ int   g_bucket[BUCKET_SLOTS];

// ---------------- helpers ----------------
__device__ __forceinline__ void red_add_v4(float* addr, float4 v) {
    asm volatile("red.global.add.v4.f32 [%0], {%1, %2, %3, %4};"
                 :: "l"(addr), "f"(v.x), "f"(v.y), "f"(v.z), "f"(v.w)
                 : "memory");
}

// ---------------- degree / norm ----------------
__global__ void k_init_deg() {
    int i = blockIdx.x * blockDim.x + threadIdx.x;
    if (i < NN) g_deg[i] = 1.0f;  // self-loop
}

__global__ void k_deg(const int* __restrict__ ei) {
    int e = blockIdx.x * blockDim.x + threadIdx.x;
    if (e < NE) atomicAdd(&g_deg[ei[NE + e]], 1.0f);  // col = target
}

__global__ void k_dinv() {
    int i = blockIdx.x * blockDim.x + threadIdx.x;
    if (i < NN) g_dinv[i] = rsqrtf(g_deg[i]);
}

// ---------------- xs = dinv ⊙ x ; tmp64 init = xs (self-loop) ----------------
__global__ void k_xs(const float* __restrict__ x) {
    int i = blockIdx.x * blockDim.x + threadIdx.x;
    if (i < NN * INCH) {
        float v = g_dinv[i >> 6] * x[i];
        g_xs[i] = v;
        g_tmp64[i] = v;
    }
}

// ---------------- 64-wide edge scatter: tmp64[c] += xs[r]  (2 edges / warp) ----------------
__global__ void k_scatter64(const int* __restrict__ ei) {
    int t = blockIdx.x * blockDim.x + threadIdx.x;
    int e = t >> 4;          // 16 lanes per edge
    int l = t & 15;
    if (e >= NE) return;
    int r = ei[e];
    int c = ei[NE + e];
    float4 v = *(const float4*)&g_xs[r * INCH + l * 4];
    red_add_v4(&g_tmp64[c * INCH + l * 4], v);
}

// ---------------- 128-wide edge scatter: tmp[c] += hws[r]  (1 edge / warp) ----------------
__global__ void k_scatter128(const int* __restrict__ ei) {
    int w = (blockIdx.x * blockDim.x + threadIdx.x) >> 5;
    int lane = threadIdx.x & 31;
    if (w >= NE) return;
    int r = ei[w];
    int c = ei[NE + w];
    float4 v = *(const float4*)&g_hws[r * EMB + lane * 4];
    red_add_v4(&g_tmp[c * EMB + lane * 4], v);
}

// ---------------- fused GCN GEMM ----------------
// out = relu( (dinv ⊙ Xin) @ W + b ), then either:
//   POOL=false: write dinv ⊙ out to g_hws and g_tmp (layer-2 scatter source + self-loop)
//   POOL=true:  red.add out into g_gsum[batch[row]]
// Register tiling: 8 rows x 4 cols per thread (block 256 = 8 warps x 32 lanes, BM=64).
template <int K, bool POOL>
__global__ void __launch_bounds__(256) k_gcn(
    const float* __restrict__ Xin, const float* __restrict__ W,
    const float* __restrict__ bias, const int* __restrict__ batch)
{
    constexpr int BM = 64;
    extern __shared__ float sm[];
    float* sW = sm;                  // K * 128
    float* sX = sm + K * 128;        // BM * (K+1)

    int tid = threadIdx.x;
    for (int i = tid; i < K * 32; i += 256)
        ((float4*)sW)[i] = ((const float4*)W)[i];

    int row0 = blockIdx.x * BM;
    for (int i = tid; i < BM * (K / 4); i += 256) {
        int r = i / (K / 4);
        int k = (i % (K / 4)) * 4;
        int gr = row0 + r;
        float4 v = make_float4(0.f, 0.f, 0.f, 0.f);
        if (gr < NN) {
            v = *(const float4*)&Xin[gr * K + k];
            float d = g_dinv[gr];
            v.x *= d; v.y *= d; v.z *= d; v.w *= d;
        }
        float* dst = &sX[r * (K + 1) + k];
        dst[0] = v.x; dst[1] = v.y; dst[2] = v.z; dst[3] = v.w;
    }
    __syncthreads();

    int warp = tid >> 5, lane = tid & 31;
    int r0 = warp * 8;
    float acc[8][4];
#pragma unroll
    for (int rr = 0; rr < 8; rr++)
        acc[rr][0] = acc[rr][1] = acc[rr][2] = acc[rr][3] = 0.f;

#pragma unroll 2
    for (int k = 0; k < K; k++) {
        float4 w4 = *(const float4*)&sW[k * 128 + lane * 4];
#pragma unroll
        for (int rr = 0; rr < 8; rr++) {
            float xv = sX[(r0 + rr) * (K + 1) + k];
            acc[rr][0] = fmaf(xv, w4.x, acc[rr][0]);
            acc[rr][1] = fmaf(xv, w4.y, acc[rr][1]);
            acc[rr][2] = fmaf(xv, w4.z, acc[rr][2]);
            acc[rr][3] = fmaf(xv, w4.w, acc[rr][3]);
        }
    }

    float4 b4 = *(const float4*)&bias[lane * 4];
#pragma unroll
    for (int rr = 0; rr < 8; rr++) {
        int gr = row0 + r0 + rr;
        if (gr >= NN) break;
        float4 o;
        o.x = fmaxf(acc[rr][0] + b4.x, 0.f);
        o.y = fmaxf(acc[rr][1] + b4.y, 0.f);
        o.z = fmaxf(acc[rr][2] + b4.z, 0.f);
        o.w = fmaxf(acc[rr][3] + b4.w, 0.f);
        if (POOL) {
            red_add_v4(&g_gsum[batch[gr] * EMB + lane * 4], o);
        } else {
            float d = g_dinv[gr];
            o.x *= d; o.y *= d; o.z *= d; o.w *= d;
            *(float4*)&g_hws[gr * EMB + lane * 4] = o;
            *(float4*)&g_tmp[gr * EMB + lane * 4] = o;   // self-loop init
        }
    }
}

// ---------------- pooling epilogue ----------------
__global__ void k_zero_graph() {
    int i = blockIdx.x * blockDim.x + threadIdx.x;
    if (i < NG * EMB) g_gsum[i] = 0.0f;
    if (i < NG) g_cnt[i] = 0.0f;
}

__global__ void k_cnt(const int* __restrict__ batch) {
    int i = blockIdx.x * blockDim.x + threadIdx.x;
    if (i < NN) atomicAdd(&g_cnt[batch[i]], 1.0f);
}

__global__ void k_ge() {
    int i = blockIdx.x * blockDim.x + threadIdx.x;
    if (i < NG * EMB) g_ge[i] = g_gsum[i] / fmaxf(g_cnt[i >> 7], 1.0f);
}

// ---------------- pair bucketing by cell line ----------------
__global__ void k_zero_bucket() {
    int i = blockIdx.x * blockDim.x + threadIdx.x;
    if (i < BUCKET_SLOTS) g_bucket[i] = -1;
    if (i < NC) { g_counts[i] = 0; g_cursor[i] = 0; }
}

__global__ void k_count(const int* __restrict__ ecl) {
    int p = blockIdx.x * blockDim.x + threadIdx.x;
    if (p < NP) atomicAdd(&g_counts[ecl[p]], 1);
}

__global__ void k_prefix() {
    int acc = 0;
    for (int c = 0; c < NC; c++) {
        g_pstart[c] = acc;
        acc += ((g_counts[c] + 31) / 32) * 32;
    }
    g_pstart[NC] = acc;
}

__global__ void k_scatter_pairs(const int* __restrict__ ecl) {
    int p = blockIdx.x * blockDim.x + threadIdx.x;
    if (p < NP) {
        int c = ecl[p];
        int pos = g_pstart[c] + atomicAdd(&g_cursor[c], 1);
        g_bucket[pos] = p;
    }
}

// ---------------- per-cell-line regressor: 32 pairs per block ----------------
__global__ void __launch_bounds__(256) k_reg(
    const int* __restrict__ ddb, const int* __restrict__ ecl,
    const float* __restrict__ w1, const float* __restrict__ b1,
    const float* __restrict__ w2, const float* __restrict__ b2,
    float* __restrict__ out)
{
    __shared__ int   s_pid[32];
    __shared__ float s_pair[32][HID];

    int tid = threadIdx.x;
    int base = blockIdx.x * 32;
    if (tid < 32) s_pid[tid] = g_bucket[base + tid];
    __syncthreads();

    int c = -1;
    for (int s = 0; s < 32 && c < 0; s++) {
        int p = s_pid[s];
        if (p >= 0) c = ecl[p];
    }
    if (c < 0) return;

    for (int i = tid; i < 32 * HID; i += 256) {
        int s = i >> 8, j = i & 255;
        int p = s_pid[s];
        float v = 0.0f;
        if (p >= 0) {
            int q = (j < 128) ? ddb[p] : ddb[NP + p];
            v = g_ge[q * EMB + (j & 127)];
        }
        s_pair[s][j] = v;
    }
    __syncthreads();

    const float* W = w1 + c * (HID * HID);
    float bt = b1[c * HID + tid];
    float acc[32];
#pragma unroll
    for (int s = 0; s < 32; s++) acc[s] = bt;

    for (int e = 0; e < HID; e += 4) {
        float wa = W[(e + 0) * HID + tid];
        float wb = W[(e + 1) * HID + tid];
        float wc = W[(e + 2) * HID + tid];
        float wd = W[(e + 3) * HID + tid];
#pragma unroll
        for (int s = 0; s < 32; s++) {
            float4 pv = *(const float4*)&s_pair[s][e];
            acc[s] = fmaf(pv.x, wa, fmaf(pv.y, wb, fmaf(pv.z, wc, fmaf(pv.w, wd, acc[s]))));
        }
    }

    float w2v = w2[c * HID + tid];
    __syncthreads();
#pragma unroll
    for (int s = 0; s < 32; s++) s_pair[s][tid] = fmaxf(acc[s], 0.0f) * w2v;
    __syncthreads();

    int s = tid >> 3, g = tid & 7;
    const float* rowp = &s_pair[s][g * 32];
    float sum = 0.0f;
#pragma unroll
    for (int j = 0; j < 32; j++) sum += rowp[j];
    sum += __shfl_down_sync(0xffffffffu, sum, 4, 8);
    sum += __shfl_down_sync(0xffffffffu, sum, 2, 8);
    sum += __shfl_down_sync(0xffffffffu, sum, 1, 8);
    if (g == 0) {
        int p = s_pid[s];
        if (p >= 0) out[p] = sum + b2[c];
    }
}

// ---------------- host launch ----------------
extern "C" void kernel_launch(void* const* d_in, const int* in_sizes, int n_in,
                              void* d_out, int out_size)
{
    const float* x    = (const float*)d_in[0];
    const float* c1w  = (const float*)d_in[1];
    const float* c1b  = (const float*)d_in[2];
    const float* c2w  = (const float*)d_in[3];
    const float* c2b  = (const float*)d_in[4];
    const float* rw1  = (const float*)d_in[5];
    const float* rb1  = (const float*)d_in[6];
    const float* rw2  = (const float*)d_in[7];
    const float* rb2  = (const float*)d_in[8];
    const int*   ei   = (const int*)d_in[9];
    const int*   bat  = (const int*)d_in[10];
    const int*   ddb  = (const int*)d_in[11];
    const int*   ecl  = (const int*)d_in[12];
    float* out = (float*)d_out;

    static bool attr_done = false;
    if (!attr_done) {
        cudaFuncSetAttribute(k_gcn<64, false>,
                             cudaFuncAttributeMaxDynamicSharedMemorySize, 49408);
        cudaFuncSetAttribute(k_gcn<128, true>,
                             cudaFuncAttributeMaxDynamicSharedMemorySize, 98560);
        attr_done = true;
    }

    float* tmp64_ptr = nullptr;
    float* tmp_ptr = nullptr;
    cudaGetSymbolAddress((void**)&tmp64_ptr, g_tmp64);
    cudaGetSymbolAddress((void**)&tmp_ptr, g_tmp);

    const int T = 256;

    // degrees / normalization
    k_init_deg<<<(NN + T - 1) / T, T>>>();
    k_deg<<<(NE + T - 1) / T, T>>>(ei);
    k_dinv<<<(NN + T - 1) / T, T>>>();

    // layer 1: aggregate in 64-dim, then transform
    k_xs<<<(NN * INCH + T - 1) / T, T>>>(x);
    k_scatter64<<<(NE * 16 + T - 1) / T, T>>>(ei);
    k_gcn<64, false><<<(NN + 63) / 64, T, 49408>>>(tmp64_ptr, c1w, c1b, nullptr);

    // layer 2: scatter 128-dim, transform fused with pooling
    k_scatter128<<<(NE * 32 + T - 1) / T, T>>>(ei);
    k_zero_graph<<<(NG * EMB + T - 1) / T, T>>>();
    k_cnt<<<(NN + T - 1) / T, T>>>(bat);
    k_gcn<128, true><<<(NN + 63) / 64, T, 98560>>>(tmp_ptr, c2w, c2b, bat);
    k_ge<<<(NG * EMB + T - 1) / T, T>>>();

    // bucket pairs by cell line
    k_zero_bucket<<<(BUCKET_SLOTS + T - 1) / T, T>>>();
    k_count<<<(NP + T - 1) / T, T>>>(ecl);
    k_prefix<<<1, 1>>>();
    k_scatter_pairs<<<(NP + T - 1) / T, T>>>(ecl);

    // regressor
    k_reg<<<REG_BLOCKS, T>>>(ddb, ecl, rw1, rb1, rw2, rb2, out);
}

// round 4
// speedup vs baseline: 1.9660x; 1.2782x over previous
#include <cuda_runtime.h>
#include <math.h>

#define NN 50000
#define NE 800000
#define NG 1024
#define NP 16384
#define NC 16
#define INCH 64
#define EMB 128
#define HID 256
#define BUCKET_SLOTS ((NP / 32 + NC) * 32)   // 16896
#define REG_BLOCKS (NP / 32 + NC)            // 528
#define NPB 128                               // nodes per scan block
#define NBLK ((NN + NPB - 1) / NPB)           // 391

// ---------------- scratch (static device memory) ----------------
__device__ float g_dinv[NN];
__device__ int   g_icnt[NN];
__device__ int   g_rowptr[NN + 1];
__device__ int   g_cursor_node[NN];
__device__ int   g_bsum[512];                 // block sums for scan
__device__ int   g_csr[NE];                   // edge sources sorted by target
__device__ float g_tmp64[NN * INCH];          // layer-1 aggregation
__device__ float g_hws[NN * EMB];             // dinv ⊙ relu(h1) (layer-2 gather source)
__device__ float g_tmp[NN * EMB];             // layer-2 aggregation
__device__ float g_gsum[NG * EMB];
__device__ float g_cnt[NG];
__device__ float g_ge[NG * EMB];
__device__ int   g_counts[NC];
__device__ int   g_cursor[NC];
__device__ int   g_pstart[NC + 1];
__device__ int   g_bucket[BUCKET_SLOTS];

// ---------------- helpers ----------------
__device__ __forceinline__ void red_add_v4(float* addr, float4 v) {
    asm volatile("red.global.add.v4.f32 [%0], {%1, %2, %3, %4};"
                 :: "l"(addr), "f"(v.x), "f"(v.y), "f"(v.z), "f"(v.w)
                 : "memory");
}
__device__ __forceinline__ float4 f4add(float4 a, float4 b) {
    return make_float4(a.x + b.x, a.y + b.y, a.z + b.z, a.w + b.w);
}

// ---------------- degree histogram + dinv ----------------
__global__ void k_zero_icnt() {
    int i = blockIdx.x * blockDim.x + threadIdx.x;
    if (i < NN) g_icnt[i] = 0;
}
__global__ void k_icnt(const int* __restrict__ ei) {
    int e = blockIdx.x * blockDim.x + threadIdx.x;
    if (e < NE) atomicAdd(&g_icnt[ei[NE + e]], 1);   // target degree
}
__global__ void k_dinv() {
    int i = blockIdx.x * blockDim.x + threadIdx.x;
    if (i < NN) g_dinv[i] = rsqrtf((float)(g_icnt[i] + 1));  // +1 self-loop
}

// ---------------- prefix scan -> rowptr ----------------
__global__ void k_scan1() {
    __shared__ int sm[NPB];
    int i = blockIdx.x * NPB + threadIdx.x;
    int v = (i < NN) ? g_icnt[i] : 0;
    sm[threadIdx.x] = v;
    __syncthreads();
    for (int s = NPB / 2; s > 0; s >>= 1) {
        if (threadIdx.x < s) sm[threadIdx.x] += sm[threadIdx.x + s];
        __syncthreads();
    }
    if (threadIdx.x == 0) g_bsum[blockIdx.x] = sm[0];
}
__global__ void k_scan2() {   // exclusive scan of g_bsum[NBLK], single block of 512
    __shared__ int sm[512];
    int t = threadIdx.x;
    int v = (t < NBLK) ? g_bsum[t] : 0;
    sm[t] = v;
    __syncthreads();
    for (int s = 1; s < 512; s <<= 1) {
        int a = (t >= s) ? sm[t - s] : 0;
        __syncthreads();
        sm[t] += a;
        __syncthreads();
    }
    if (t < NBLK) g_bsum[t] = sm[t] - v;   // exclusive
}
__global__ void k_scan3() {
    __shared__ int sm[NPB];
    int t = threadIdx.x;
    int i = blockIdx.x * NPB + t;
    int v = (i < NN) ? g_icnt[i] : 0;
    sm[t] = v;
    __syncthreads();
    for (int s = 1; s < NPB; s <<= 1) {
        int a = (t >= s) ? sm[t - s] : 0;
        __syncthreads();
        sm[t] += a;
        __syncthreads();
    }
    if (i < NN) {
        int p = g_bsum[blockIdx.x] + sm[t] - v;   // exclusive prefix
        g_rowptr[i] = p;
        g_cursor_node[i] = p;
        if (i == NN - 1) g_rowptr[NN] = NE;
    }
}
__global__ void k_fill(const int* __restrict__ ei) {
    int e = blockIdx.x * blockDim.x + threadIdx.x;
    if (e < NE) {
        int c = ei[NE + e];
        int pos = atomicAdd(&g_cursor_node[c], 1);
        g_csr[pos] = ei[e];   // source
    }
}

// ---------------- layer-1 gather: tmp64[n] = dinv[n]*x[n] + Σ dinv[s]*x[s] ----------------
// half-warp per node (16 lanes x float4 = 64 floats)
__global__ void __launch_bounds__(256) k_gather64(const float* __restrict__ x) {
    int warp = (blockIdx.x * 256 + threadIdx.x) >> 5;
    int lane = threadIdx.x & 31;
    int half = lane >> 4, l = lane & 15;
    int node = warp * 2 + half;
    if (node >= NN) return;

    float4 acc = *(const float4*)&x[node * INCH + l * 4];
    float d = g_dinv[node];
    acc.x *= d; acc.y *= d; acc.z *= d; acc.w *= d;

    int e = g_rowptr[node], end = g_rowptr[node + 1];
    for (; e + 4 <= end; e += 4) {
        int s0 = g_csr[e], s1 = g_csr[e + 1], s2 = g_csr[e + 2], s3 = g_csr[e + 3];
        float4 a = *(const float4*)&x[s0 * INCH + l * 4];
        float4 b = *(const float4*)&x[s1 * INCH + l * 4];
        float4 c = *(const float4*)&x[s2 * INCH + l * 4];
        float4 dd = *(const float4*)&x[s3 * INCH + l * 4];
        float d0 = g_dinv[s0], d1 = g_dinv[s1], d2 = g_dinv[s2], d3 = g_dinv[s3];
        acc.x = fmaf(d0, a.x, fmaf(d1, b.x, fmaf(d2, c.x, fmaf(d3, dd.x, acc.x))));
        acc.y = fmaf(d0, a.y, fmaf(d1, b.y, fmaf(d2, c.y, fmaf(d3, dd.y, acc.y))));
        acc.z = fmaf(d0, a.z, fmaf(d1, b.z, fmaf(d2, c.z, fmaf(d3, dd.z, acc.z))));
        acc.w = fmaf(d0, a.w, fmaf(d1, b.w, fmaf(d2, c.w, fmaf(d3, dd.w, acc.w))));
    }
    for (; e < end; e++) {
        int s = g_csr[e];
        float4 a = *(const float4*)&x[s * INCH + l * 4];
        float ds = g_dinv[s];
        acc.x = fmaf(ds, a.x, acc.x);
        acc.y = fmaf(ds, a.y, acc.y);
        acc.z = fmaf(ds, a.z, acc.z);
        acc.w = fmaf(ds, a.w, acc.w);
    }
    *(float4*)&g_tmp64[node * INCH + l * 4] = acc;
}

// ---------------- layer-2 gather: tmp[n] = hws[n] + Σ hws[s]  (warp per node) ----------------
__global__ void __launch_bounds__(256) k_gather128() {
    int node = (blockIdx.x * 256 + threadIdx.x) >> 5;
    int lane = threadIdx.x & 31;
    if (node >= NN) return;

    float4 acc = *(const float4*)&g_hws[node * EMB + lane * 4];  // self (already dinv-scaled)

    int e = g_rowptr[node], end = g_rowptr[node + 1];
    for (; e + 4 <= end; e += 4) {
        int s0 = g_csr[e], s1 = g_csr[e + 1], s2 = g_csr[e + 2], s3 = g_csr[e + 3];
        float4 a = *(const float4*)&g_hws[s0 * EMB + lane * 4];
        float4 b = *(const float4*)&g_hws[s1 * EMB + lane * 4];
        float4 c = *(const float4*)&g_hws[s2 * EMB + lane * 4];
        float4 d = *(const float4*)&g_hws[s3 * EMB + lane * 4];
        acc = f4add(acc, f4add(f4add(a, b), f4add(c, d)));
    }
    for (; e < end; e++) {
        int s = g_csr[e];
        acc = f4add(acc, *(const float4*)&g_hws[s * EMB + lane * 4]);
    }
    *(float4*)&g_tmp[node * EMB + lane * 4] = acc;
}

// ---------------- fused GCN GEMM ----------------
// out = relu( (dinv ⊙ Xin) @ W + b ), then:
//   POOL=false: write dinv ⊙ out to g_hws
//   POOL=true:  red.add out into g_gsum[batch[row]]
template <int K, bool POOL>
__global__ void __launch_bounds__(256) k_gcn(
    const float* __restrict__ Xin, const float* __restrict__ W,
    const float* __restrict__ bias, const int* __restrict__ batch)
{
    constexpr int BM = 64;
    extern __shared__ float sm[];
    float* sW = sm;                  // K * 128
    float* sX = sm + K * 128;        // BM * (K+1)

    int tid = threadIdx.x;
    for (int i = tid; i < K * 32; i += 256)
        ((float4*)sW)[i] = ((const float4*)W)[i];

    int row0 = blockIdx.x * BM;
    for (int i = tid; i < BM * (K / 4); i += 256) {
        int r = i / (K / 4);
        int k = (i % (K / 4)) * 4;
        int gr = row0 + r;
        float4 v = make_float4(0.f, 0.f, 0.f, 0.f);
        if (gr < NN) {
            v = *(const float4*)&Xin[gr * K + k];
            float d = g_dinv[gr];
            v.x *= d; v.y *= d; v.z *= d; v.w *= d;
        }
        float* dst = &sX[r * (K + 1) + k];
        dst[0] = v.x; dst[1] = v.y; dst[2] = v.z; dst[3] = v.w;
    }
    __syncthreads();

    int warp = tid >> 5, lane = tid & 31;
    int r0 = warp * 8;
    float acc[8][4];
#pragma unroll
    for (int rr = 0; rr < 8; rr++)
        acc[rr][0] = acc[rr][1] = acc[rr][2] = acc[rr][3] = 0.f;

#pragma unroll 2
    for (int k = 0; k < K; k++) {
        float4 w4 = *(const float4*)&sW[k * 128 + lane * 4];
#pragma unroll
        for (int rr = 0; rr < 8; rr++) {
            float xv = sX[(r0 + rr) * (K + 1) + k];
            acc[rr][0] = fmaf(xv, w4.x, acc[rr][0]);
            acc[rr][1] = fmaf(xv, w4.y, acc[rr][1]);
            acc[rr][2] = fmaf(xv, w4.z, acc[rr][2]);
            acc[rr][3] = fmaf(xv, w4.w, acc[rr][3]);
        }
    }

    float4 b4 = *(const float4*)&bias[lane * 4];
#pragma unroll
    for (int rr = 0; rr < 8; rr++) {
        int gr = row0 + r0 + rr;
        if (gr >= NN) break;
        float4 o;
        o.x = fmaxf(acc[rr][0] + b4.x, 0.f);
        o.y = fmaxf(acc[rr][1] + b4.y, 0.f);
        o.z = fmaxf(acc[rr][2] + b4.z, 0.f);
        o.w = fmaxf(acc[rr][3] + b4.w, 0.f);
        if (POOL) {
            red_add_v4(&g_gsum[batch[gr] * EMB + lane * 4], o);
        } else {
            float d = g_dinv[gr];
            o.x *= d; o.y *= d; o.z *= d; o.w *= d;
            *(float4*)&g_hws[gr * EMB + lane * 4] = o;
        }
    }
}

// ---------------- pooling epilogue ----------------
__global__ void k_zero_graph() {
    int i = blockIdx.x * blockDim.x + threadIdx.x;
    if (i < NG * EMB) g_gsum[i] = 0.0f;
    if (i < NG) g_cnt[i] = 0.0f;
}
__global__ void k_cnt(const int* __restrict__ batch) {
    int i = blockIdx.x * blockDim.x + threadIdx.x;
    if (i < NN) atomicAdd(&g_cnt[batch[i]], 1.0f);
}
__global__ void k_ge() {
    int i = blockIdx.x * blockDim.x + threadIdx.x;
    if (i < NG * EMB) g_ge[i] = g_gsum[i] / fmaxf(g_cnt[i >> 7], 1.0f);
}

// ---------------- pair bucketing by cell line ----------------
__global__ void k_zero_bucket() {
    int i = blockIdx.x * blockDim.x + threadIdx.x;
    if (i < BUCKET_SLOTS) g_bucket[i] = -1;
    if (i < NC) { g_counts[i] = 0; g_cursor[i] = 0; }
}
__global__ void k_count(const int* __restrict__ ecl) {
    int p = blockIdx.x * blockDim.x + threadIdx.x;
    if (p < NP) atomicAdd(&g_counts[ecl[p]], 1);
}
__global__ void k_prefix() {
    int acc = 0;
    for (int c = 0; c < NC; c++) {
        g_pstart[c] = acc;
        acc += ((g_counts[c] + 31) / 32) * 32;
    }
    g_pstart[NC] = acc;
}
__global__ void k_scatter_pairs(const int* __restrict__ ecl) {
    int p = blockIdx.x * blockDim.x + threadIdx.x;
    if (p < NP) {
        int c = ecl[p];
        int pos = g_pstart[c] + atomicAdd(&g_cursor[c], 1);
        g_bucket[pos] = p;
    }
}

// ---------------- per-cell-line regressor: 32 pairs per block ----------------
__global__ void __launch_bounds__(256) k_reg(
    const int* __restrict__ ddb, const int* __restrict__ ecl,
    const float* __restrict__ w1, const float* __restrict__ b1,
    const float* __restrict__ w2, const float* __restrict__ b2,
    float* __restrict__ out)
{
    __shared__ int   s_pid[32];
    __shared__ float s_pair[32][HID];

    int tid = threadIdx.x;
    int base = blockIdx.x * 32;
    if (tid < 32) s_pid[tid] = g_bucket[base + tid];
    __syncthreads();

    int c = -1;
    for (int s = 0; s < 32 && c < 0; s++) {
        int p = s_pid[s];
        if (p >= 0) c = ecl[p];
    }
    if (c < 0) return;

    for (int i = tid; i < 32 * HID; i += 256) {
        int s = i >> 8, j = i & 255;
        int p = s_pid[s];
        float v = 0.0f;
        if (p >= 0) {
            int q = (j < 128) ? ddb[p] : ddb[NP + p];
            v = g_ge[q * EMB + (j & 127)];
        }
        s_pair[s][j] = v;
    }
    __syncthreads();

    const float* W = w1 + c * (HID * HID);
    float bt = b1[c * HID + tid];
    float acc[32];
#pragma unroll
    for (int s = 0; s < 32; s++) acc[s] = bt;

    for (int e = 0; e < HID; e += 4) {
        float wa = W[(e + 0) * HID + tid];
        float wb = W[(e + 1) * HID + tid];
        float wc = W[(e + 2) * HID + tid];
        float wd = W[(e + 3) * HID + tid];
#pragma unroll
        for (int s = 0; s < 32; s++) {
            float4 pv = *(const float4*)&s_pair[s][e];
            acc[s] = fmaf(pv.x, wa, fmaf(pv.y, wb, fmaf(pv.z, wc, fmaf(pv.w, wd, acc[s]))));
        }
    }

    float w2v = w2[c * HID + tid];
    __syncthreads();
#pragma unroll
    for (int s = 0; s < 32; s++) s_pair[s][tid] = fmaxf(acc[s], 0.0f) * w2v;
    __syncthreads();

    int s = tid >> 3, g = tid & 7;
    const float* rowp = &s_pair[s][g * 32];
    float sum = 0.0f;
#pragma unroll
    for (int j = 0; j < 32; j++) sum += rowp[j];
    sum += __shfl_down_sync(0xffffffffu, sum, 4, 8);
    sum += __shfl_down_sync(0xffffffffu, sum, 2, 8);
    sum += __shfl_down_sync(0xffffffffu, sum, 1, 8);
    if (g == 0) {
        int p = s_pid[s];
        if (p >= 0) out[p] = sum + b2[c];
    }
}

// ---------------- host launch ----------------
extern "C" void kernel_launch(void* const* d_in, const int* in_sizes, int n_in,
                              void* d_out, int out_size)
{
    const float* x    = (const float*)d_in[0];
    const float* c1w  = (const float*)d_in[1];
    const float* c1b  = (const float*)d_in[2];
    const float* c2w  = (const float*)d_in[3];
    const float* c2b  = (const float*)d_in[4];
    const float* rw1  = (const float*)d_in[5];
    const float* rb1  = (const float*)d_in[6];
    const float* rw2  = (const float*)d_in[7];
    const float* rb2  = (const float*)d_in[8];
    const int*   ei   = (const int*)d_in[9];
    const int*   bat  = (const int*)d_in[10];
    const int*   ddb  = (const int*)d_in[11];
    const int*   ecl  = (const int*)d_in[12];
    float* out = (float*)d_out;

    static bool attr_done = false;
    if (!attr_done) {
        cudaFuncSetAttribute(k_gcn<64, false>,
                             cudaFuncAttributeMaxDynamicSharedMemorySize, 49408);
        cudaFuncSetAttribute(k_gcn<128, true>,
                             cudaFuncAttributeMaxDynamicSharedMemorySize, 98560);
        attr_done = true;
    }

    float* tmp64_ptr = nullptr;
    float* tmp_ptr = nullptr;
    cudaGetSymbolAddress((void**)&tmp64_ptr, g_tmp64);
    cudaGetSymbolAddress((void**)&tmp_ptr, g_tmp);

    const int T = 256;

    // degree histogram + dinv + CSR build
    k_zero_icnt<<<(NN + T - 1) / T, T>>>();
    k_icnt<<<(NE + T - 1) / T, T>>>(ei);
    k_dinv<<<(NN + T - 1) / T, T>>>();
    k_scan1<<<NBLK, NPB>>>();
    k_scan2<<<1, 512>>>();
    k_scan3<<<NBLK, NPB>>>();
    k_fill<<<(NE + T - 1) / T, T>>>(ei);

    // layer 1: gather in 64-dim, then transform
    k_gather64<<<(NN / 2 + 7) / 8, T>>>(x);
    k_gcn<64, false><<<(NN + 63) / 64, T, 49408>>>(tmp64_ptr, c1w, c1b, nullptr);

    // layer 2: gather 128-dim, transform fused with pooling
    k_gather128<<<(NN + 7) / 8, T>>>();
    k_zero_graph<<<(NG * EMB + T - 1) / T, T>>>();
    k_cnt<<<(NN + T - 1) / T, T>>>(bat);
    k_gcn<128, true><<<(NN + 63) / 64, T, 98560>>>(tmp_ptr, c2w, c2b, bat);
    k_ge<<<(NG * EMB + T - 1) / T, T>>>();

    // bucket pairs by cell line
    k_zero_bucket<<<(BUCKET_SLOTS + T - 1) / T, T>>>();
    k_count<<<(NP + T - 1) / T, T>>>(ecl);
    k_prefix<<<1, 1>>>();
    k_scatter_pairs<<<(NP + T - 1) / T, T>>>(ecl);

    // regressor
    k_reg<<<REG_BLOCKS, T>>>(ddb, ecl, rw1, rb1, rw2, rb2, out);
}